// round 2
// baseline (speedup 1.0000x reference)
#include <cuda_runtime.h>
#include <math.h>

#define BB 4
#define CCH 64
#define HH 192
#define WWD 192
#define HWSZ (HH*WWD)          // 36864
#define NPIX (BB*HWSZ)         // 147456

// ---------------- scratch (device globals; no allocation allowed) ----------
__device__ float g_off  [BB*18*HWSZ];
__device__ float g_mask [BB*9 *HWSZ];
__device__ float g_xd   [BB*CCH*HWSZ];
__device__ float g_xa   [BB*CCH*HWSZ];
__device__ float g_r1   [BB*256*HWSZ];
__device__ float g_xr   [BB*CCH*HWSZ];
__device__ float g_n1   [BB*32*HWSZ];
__device__ float g_n2   [BB*32*HWSZ];
__device__ float g_camean[BB*CCH];
__device__ float g_ca   [BB*CCH];

// transposed weights (output-channel contiguous for float4 shared loads)
__device__ float g_woffT[64*9*28];    // [c][k][o pad28]
__device__ float g_wdcT [9*64*64];    // [k][c][o]
__device__ float g_wr1T [64*256];     // [c][o]
__device__ float g_wr2T [256*9*64];   // [c][k][o]
__device__ float g_wn1T [64*32];      // [c][o]
__device__ float g_wn3T [32*64];      // [c][o]

__device__ __forceinline__ float leakyf(float v){ return v >= 0.f ? v : 0.1f*v; }
__device__ __forceinline__ float sigmf(float v){ return 1.f/(1.f+__expf(-v)); }

// ---------------- weight transpose prep ------------------------------------
__global__ void k_prep(const float* __restrict__ w_off, const float* __restrict__ w_dc,
                       const float* __restrict__ w_r1,  const float* __restrict__ w_r2,
                       const float* __restrict__ w_n1,  const float* __restrict__ w_n3){
    int t = blockIdx.x*blockDim.x + threadIdx.x;
    int nt = gridDim.x*blockDim.x;
    for (int i=t;i<64*9*28;i+=nt){ int o=i%28; int k=(i/28)%9; int c=i/(28*9);
        g_woffT[i] = (o<27) ? w_off[(o*64+c)*9+k] : 0.f; }
    for (int i=t;i<9*64*64;i+=nt){ int o=i%64; int c=(i/64)%64; int k=i/(64*64);
        g_wdcT[i] = w_dc[(o*64+c)*9+k]; }
    for (int i=t;i<64*256;i+=nt){ int o=i%256; int c=i/256; g_wr1T[i]=w_r1[o*64+c]; }
    for (int i=t;i<256*9*64;i+=nt){ int o=i%64; int k=(i/64)%9; int c=i/(64*9);
        g_wr2T[i] = w_r2[(o*256+c)*9+k]; }
    for (int i=t;i<64*32;i+=nt){ int o=i%32; int c=i/32; g_wn1T[i]=w_n1[o*64+c]; }
    for (int i=t;i<32*64;i+=nt){ int o=i%64; int c=i/64; g_wn3T[i]=w_n3[o*32+c]; }
}

// ---------------- offset conv: 3x3 64->27, leaky, split off/mask ------------
__global__ void k_off(const float* __restrict__ x, const float* __restrict__ b_off){
    __shared__ float sW[16*9*28];      // 16.1KB
    int p = blockIdx.x*blockDim.x + threadIdx.x;
    bool act = p < NPIX;
    int b=0,h=0,w=0,hw=0;
    if (act){ b=p/HWSZ; hw=p%HWSZ; h=hw/WWD; w=hw%WWD; }
    float acc[28];
    #pragma unroll
    for (int o=0;o<28;o++) acc[o] = (o<27) ? b_off[o] : 0.f;
    int toff[9]; bool tv[9];
    #pragma unroll
    for (int k=0;k<9;k++){
        int hy=h+k/3-1, wx=w+k%3-1;
        tv[k] = (hy>=0 && hy<HH && wx>=0 && wx<WWD);
        toff[k] = tv[k] ? hy*WWD+wx : 0;
    }
    for (int cc=0; cc<4; cc++){
        for (int j=threadIdx.x; j<16*9*28; j+=blockDim.x) sW[j]=g_woffT[cc*16*9*28 + j];
        __syncthreads();
        if (act){
            const float* xb = x + (b*64 + cc*16)*HWSZ;
            for (int c=0;c<16;c++){
                const float* xc = xb + c*HWSZ;
                float xv[9];
                #pragma unroll
                for (int k=0;k<9;k++) xv[k] = tv[k] ? xc[toff[k]] : 0.f;
                const float4* wp = (const float4*)&sW[c*9*28];
                #pragma unroll
                for (int k=0;k<9;k++){
                    float v = xv[k];
                    #pragma unroll
                    for (int j=0;j<7;j++){
                        float4 ww = wp[k*7+j];
                        acc[4*j+0]+=v*ww.x; acc[4*j+1]+=v*ww.y;
                        acc[4*j+2]+=v*ww.z; acc[4*j+3]+=v*ww.w;
                    }
                }
            }
        }
        __syncthreads();
    }
    if (act){
        #pragma unroll
        for (int o=0;o<18;o++) g_off[(b*18+o)*HWSZ+hw] = leakyf(acc[o]);
        #pragma unroll
        for (int o=0;o<9;o++)  g_mask[(b*9+o)*HWSZ+hw] = sigmf(leakyf(acc[18+o]));
    }
}

// ---------------- deformable conv 64->64 -----------------------------------
__global__ void k_dc(const float* __restrict__ x, const float* __restrict__ b_dc){
    __shared__ float sW[64*64];        // 16KB, [c][o] for current k
    int p = blockIdx.x*blockDim.x + threadIdx.x;
    bool act = p < NPIX;
    int b=0,h=0,w=0,hw=0;
    if (act){ b=p/HWSZ; hw=p%HWSZ; h=hw/WWD; w=hw%WWD; }
    float acc[64];
    #pragma unroll
    for (int o=0;o<64;o++) acc[o]=0.f;
    for (int k=0;k<9;k++){
        for (int j=threadIdx.x;j<64*64;j+=blockDim.x) sW[j]=g_wdcT[k*64*64+j];
        __syncthreads();
        if (act){
            float dy = g_off[(b*18+2*k  )*HWSZ+hw];
            float dx = g_off[(b*18+2*k+1)*HWSZ+hw];
            float m  = g_mask[(b*9+k)*HWSZ+hw];
            float py = (float)h + (float)(k/3-1) + dy;
            float px = (float)w + (float)(k%3-1) + dx;
            float y0f = floorf(py), x0f = floorf(px);
            float wy = py - y0f,  wx = px - x0f;
            int y0=(int)y0f, x0=(int)x0f, y1=y0+1, x1=x0+1;
            bool vy0=(y0>=0&&y0<HH), vy1=(y1>=0&&y1<HH);
            bool vx0=(x0>=0&&x0<WWD), vx1=(x1>=0&&x1<WWD);
            float w00=(1.f-wy)*(1.f-wx)*((vy0&&vx0)?m:0.f);
            float w01=(1.f-wy)*wx      *((vy0&&vx1)?m:0.f);
            float w10=wy*(1.f-wx)      *((vy1&&vx0)?m:0.f);
            float w11=wy*wx            *((vy1&&vx1)?m:0.f);
            int cy0=min(max(y0,0),HH-1), cy1=min(max(y1,0),HH-1);
            int cx0=min(max(x0,0),WWD-1), cx1=min(max(x1,0),WWD-1);
            int i00=cy0*WWD+cx0, i01=cy0*WWD+cx1, i10=cy1*WWD+cx0, i11=cy1*WWD+cx1;
            const float* xb = x + b*64*HWSZ;
            for (int c=0;c<64;c++){
                const float* xc = xb + c*HWSZ;
                float v = w00*xc[i00]+w01*xc[i01]+w10*xc[i10]+w11*xc[i11];
                const float4* wp = (const float4*)&sW[c*64];
                #pragma unroll
                for (int j=0;j<16;j++){
                    float4 ww = wp[j];
                    acc[4*j+0]+=v*ww.x; acc[4*j+1]+=v*ww.y;
                    acc[4*j+2]+=v*ww.z; acc[4*j+3]+=v*ww.w;
                }
            }
        }
        __syncthreads();
    }
    if (act){
        #pragma unroll
        for (int o=0;o<64;o++) g_xd[(b*64+o)*HWSZ+hw] = acc[o] + b_dc[o];
    }
}

// ---------------- channel-attention mean reduce ------------------------------
__global__ void k_ca_red(){
    int bc = blockIdx.x;               // 0..255  (b*64+c)
    const float* src = g_xd + (size_t)bc*HWSZ;
    float s = 0.f;
    for (int i=threadIdx.x;i<HWSZ;i+=blockDim.x) s += src[i];
    __shared__ float red[256];
    red[threadIdx.x]=s; __syncthreads();
    for (int st=128;st>0;st>>=1){ if (threadIdx.x<st) red[threadIdx.x]+=red[threadIdx.x+st]; __syncthreads(); }
    if (threadIdx.x==0) g_camean[bc] = red[0]*(1.f/(float)HWSZ);
}

// ---------------- channel-attention MLP (tiny) ------------------------------
__global__ void k_ca_mlp(const float* __restrict__ w_ca1, const float* __restrict__ b_ca1,
                         const float* __restrict__ w_ca2, const float* __restrict__ b_ca2){
    __shared__ float hid[4*8];
    int t = threadIdx.x;
    if (t<32){ int b=t/8, j=t%8;
        float s = b_ca1[j];
        for (int c=0;c<64;c++) s += w_ca1[j*64+c]*g_camean[b*64+c];
        hid[b*8+j] = fmaxf(s,0.f);
    }
    __syncthreads();
    if (t<256){ int b=t/64, o=t%64;
        float s = b_ca2[o];
        #pragma unroll
        for (int j=0;j<8;j++) s += w_ca2[o*8+j]*hid[b*8+j];
        g_ca[t] = sigmf(s);
    }
}

// ---------------- spatial attention + xa = xd*(ca+sa) ------------------------
__global__ void k_sa_xa(const float* __restrict__ w_sa, const float* __restrict__ b_sa){
    __shared__ float sW[64*9];
    for (int j=threadIdx.x;j<576;j+=blockDim.x) sW[j]=w_sa[j];
    __syncthreads();
    int p = blockIdx.x*blockDim.x + threadIdx.x;
    if (p>=NPIX) return;
    int b=p/HWSZ, hw=p%HWSZ, h=hw/WWD, w=hw%WWD;
    int toff[9]; bool tv[9];
    #pragma unroll
    for (int k=0;k<9;k++){
        int hy=h+k/3-1, wx=w+k%3-1;
        tv[k]=(hy>=0&&hy<HH&&wx>=0&&wx<WWD);
        toff[k]=tv[k]?hy*WWD+wx:0;
    }
    float s = b_sa[0];
    const float* xb = g_xd + b*64*HWSZ;
    for (int c=0;c<64;c++){
        const float* xc = xb + c*HWSZ;
        #pragma unroll
        for (int k=0;k<9;k++) if (tv[k]) s += xc[toff[k]]*sW[c*9+k];
    }
    s = sigmf(s);
    for (int c=0;c<64;c++){
        float scale = g_ca[b*64+c] + s;
        g_xa[(b*64+c)*HWSZ+hw] = xb[c*HWSZ+hw]*scale;
    }
}

// ---------------- r1: conv1x1 64->256 + leaky (oc chunks of 64) --------------
__global__ void k_r1(const float* __restrict__ b_r1){
    __shared__ float sW[64*64];
    int oc0 = blockIdx.y*64;
    for (int j=threadIdx.x;j<4096;j+=blockDim.x){ int c=j>>6, o=j&63; sW[j]=g_wr1T[c*256+oc0+o]; }
    __syncthreads();
    int p = blockIdx.x*blockDim.x + threadIdx.x;
    if (p>=NPIX) return;
    int b=p/HWSZ, hw=p%HWSZ;
    float acc[64];
    #pragma unroll
    for (int o=0;o<64;o++) acc[o]=b_r1[oc0+o];
    const float* xb = g_xa + b*64*HWSZ + hw;
    for (int c=0;c<64;c++){
        float v = xb[(size_t)c*HWSZ];
        const float4* wp = (const float4*)&sW[c*64];
        #pragma unroll
        for (int j=0;j<16;j++){
            float4 ww = wp[j];
            acc[4*j+0]+=v*ww.x; acc[4*j+1]+=v*ww.y;
            acc[4*j+2]+=v*ww.z; acc[4*j+3]+=v*ww.w;
        }
    }
    float* ob = g_r1 + ((size_t)b*256+oc0)*HWSZ + hw;
    #pragma unroll
    for (int o=0;o<64;o++) ob[(size_t)o*HWSZ] = leakyf(acc[o]);
}

// ---------------- r2: conv3x3 256->64 ----------------------------------------
__global__ void k_r2(const float* __restrict__ b_r2){
    __shared__ float sW[16*9*64];      // 36.9KB
    int p = blockIdx.x*blockDim.x + threadIdx.x;
    bool act = p<NPIX;
    int b=0,h=0,w=0,hw=0;
    if (act){ b=p/HWSZ; hw=p%HWSZ; h=hw/WWD; w=hw%WWD; }
    int toff[9]; bool tv[9];
    #pragma unroll
    for (int k=0;k<9;k++){
        int hy=h+k/3-1, wx=w+k%3-1;
        tv[k]=(hy>=0&&hy<HH&&wx>=0&&wx<WWD);
        toff[k]=tv[k]?hy*WWD+wx:0;
    }
    float acc[64];
    #pragma unroll
    for (int o=0;o<64;o++) acc[o]=0.f;
    for (int cc=0; cc<16; cc++){
        for (int j=threadIdx.x;j<16*9*64;j+=blockDim.x) sW[j]=g_wr2T[cc*16*9*64 + j];
        __syncthreads();
        if (act){
            const float* xb = g_r1 + ((size_t)b*256 + cc*16)*HWSZ;
            for (int c=0;c<16;c++){
                const float* xc = xb + (size_t)c*HWSZ;
                float xv[9];
                #pragma unroll
                for (int k=0;k<9;k++) xv[k] = tv[k] ? xc[toff[k]] : 0.f;
                const float4* wp = (const float4*)&sW[c*9*64];
                #pragma unroll
                for (int k=0;k<9;k++){
                    float v = xv[k];
                    #pragma unroll
                    for (int j=0;j<16;j++){
                        float4 ww = wp[k*16+j];
                        acc[4*j+0]+=v*ww.x; acc[4*j+1]+=v*ww.y;
                        acc[4*j+2]+=v*ww.z; acc[4*j+3]+=v*ww.w;
                    }
                }
            }
        }
        __syncthreads();
    }
    if (act){
        #pragma unroll
        for (int o=0;o<64;o++) g_xr[((size_t)b*64+o)*HWSZ+hw] = acc[o] + b_r2[o];
    }
}

// ---------------- n1: conv1x1 64->32 ----------------------------------------
__global__ void k_n1(const float* __restrict__ b_n1){
    __shared__ float sW[64*32];        // 8KB
    for (int j=threadIdx.x;j<2048;j+=blockDim.x) sW[j]=g_wn1T[j];
    __syncthreads();
    int p = blockIdx.x*blockDim.x + threadIdx.x;
    if (p>=NPIX) return;
    int b=p/HWSZ, hw=p%HWSZ;
    float acc[32];
    #pragma unroll
    for (int o=0;o<32;o++) acc[o]=b_n1[o];
    const float* xb = g_xa + (size_t)b*64*HWSZ + hw;
    for (int c=0;c<64;c++){
        float v = xb[(size_t)c*HWSZ];
        const float4* wp=(const float4*)&sW[c*32];
        #pragma unroll
        for (int j=0;j<8;j++){
            float4 ww=wp[j];
            acc[4*j+0]+=v*ww.x; acc[4*j+1]+=v*ww.y;
            acc[4*j+2]+=v*ww.z; acc[4*j+3]+=v*ww.w;
        }
    }
    float* ob = g_n1 + (size_t)b*32*HWSZ + hw;
    #pragma unroll
    for (int o=0;o<32;o++) ob[(size_t)o*HWSZ]=acc[o];
}

// ---------------- n2: depthwise 3x3 (32 ch) ----------------------------------
__global__ void k_n2(const float* __restrict__ w_n2, const float* __restrict__ b_n2){
    __shared__ float sW[32*9];
    for (int j=threadIdx.x;j<288;j+=blockDim.x) sW[j]=w_n2[j];
    __syncthreads();
    int p = blockIdx.x*blockDim.x + threadIdx.x;
    if (p>=NPIX) return;
    int b=p/HWSZ, hw=p%HWSZ, h=hw/WWD, w=hw%WWD;
    int toff[9]; bool tv[9];
    #pragma unroll
    for (int k=0;k<9;k++){
        int hy=h+k/3-1, wx=w+k%3-1;
        tv[k]=(hy>=0&&hy<HH&&wx>=0&&wx<WWD);
        toff[k]=tv[k]?hy*WWD+wx:0;
    }
    const float* xb = g_n1 + (size_t)b*32*HWSZ;
    float* ob = g_n2 + (size_t)b*32*HWSZ;
    for (int c=0;c<32;c++){
        const float* xc = xb + (size_t)c*HWSZ;
        float acc = b_n2[c];
        #pragma unroll
        for (int k=0;k<9;k++) if (tv[k]) acc += xc[toff[k]]*sW[c*9+k];
        ob[(size_t)c*HWSZ+hw]=acc;
    }
}

// ---------------- final: conv1x1 32->64 (n3) + x + xr -> out ------------------
__global__ void k_final(const float* __restrict__ x, const float* __restrict__ b_n3,
                        float* __restrict__ out){
    __shared__ float sW[32*64];        // 8KB
    for (int j=threadIdx.x;j<2048;j+=blockDim.x) sW[j]=g_wn3T[j];
    __syncthreads();
    int p = blockIdx.x*blockDim.x + threadIdx.x;
    if (p>=NPIX) return;
    int b=p/HWSZ, hw=p%HWSZ;
    float acc[64];
    #pragma unroll
    for (int o=0;o<64;o++) acc[o]=b_n3[o];
    const float* xb = g_n2 + (size_t)b*32*HWSZ + hw;
    for (int c=0;c<32;c++){
        float v = xb[(size_t)c*HWSZ];
        const float4* wp=(const float4*)&sW[c*64];
        #pragma unroll
        for (int j=0;j<16;j++){
            float4 ww=wp[j];
            acc[4*j+0]+=v*ww.x; acc[4*j+1]+=v*ww.y;
            acc[4*j+2]+=v*ww.z; acc[4*j+3]+=v*ww.w;
        }
    }
    const float* xin = x + (size_t)b*64*HWSZ + hw;
    const float* xr  = g_xr + (size_t)b*64*HWSZ + hw;
    float* ob = out + (size_t)b*64*HWSZ + hw;
    #pragma unroll
    for (int o=0;o<64;o++)
        ob[(size_t)o*HWSZ] = xin[(size_t)o*HWSZ] + xr[(size_t)o*HWSZ] + acc[o];
}

// ---------------- launch ------------------------------------------------------
extern "C" void kernel_launch(void* const* d_in, const int* in_sizes, int n_in,
                              void* d_out, int out_size){
    const float* x     = (const float*)d_in[0];
    const float* w_off = (const float*)d_in[1];
    const float* b_off = (const float*)d_in[2];
    const float* w_dc  = (const float*)d_in[3];
    const float* b_dc  = (const float*)d_in[4];
    const float* w_ca1 = (const float*)d_in[5];
    const float* b_ca1 = (const float*)d_in[6];
    const float* w_ca2 = (const float*)d_in[7];
    const float* b_ca2 = (const float*)d_in[8];
    const float* w_sa  = (const float*)d_in[9];
    const float* b_sa  = (const float*)d_in[10];
    const float* w_r1  = (const float*)d_in[11];
    const float* b_r1  = (const float*)d_in[12];
    const float* w_r2  = (const float*)d_in[13];
    const float* b_r2  = (const float*)d_in[14];
    const float* w_n1  = (const float*)d_in[15];
    const float* b_n1  = (const float*)d_in[16];
    const float* w_n2  = (const float*)d_in[17];
    const float* b_n2  = (const float*)d_in[18];
    const float* w_n3  = (const float*)d_in[19];
    const float* b_n3  = (const float*)d_in[20];
    float* out = (float*)d_out;

    const int TPB = 256;
    const int GP  = (NPIX + TPB - 1)/TPB;   // 576

    k_prep<<<64, 256>>>(w_off, w_dc, w_r1, w_r2, w_n1, w_n3);
    k_off<<<GP, TPB>>>(x, b_off);
    k_dc<<<GP, TPB>>>(x, b_dc);
    k_ca_red<<<BB*CCH, 256>>>();
    k_ca_mlp<<<1, 256>>>(w_ca1, b_ca1, w_ca2, b_ca2);
    k_sa_xa<<<GP, TPB>>>(w_sa, b_sa);
    k_r1<<<dim3(GP,4), TPB>>>(b_r1);
    k_r2<<<GP, TPB>>>(b_r2);
    k_n1<<<GP, TPB>>>(b_n1);
    k_n2<<<GP, TPB>>>(w_n2, b_n2);
    k_final<<<GP, TPB>>>(x, b_n3, out);
}

// round 5
// speedup vs baseline: 1.1922x; 1.1922x over previous
#include <cuda_runtime.h>
#include <math.h>

#define BB 4
#define CCH 64
#define HH 192
#define WWD 192
#define HWSZ (HH*WWD)          // 36864
#define NPIX (BB*HWSZ)         // 147456

typedef unsigned long long u64;

// ---------------- packed f32x2 helpers (FFMA2) ------------------------------
__device__ __forceinline__ u64 pk2(float a, float b){
    u64 r; asm("mov.b64 %0, {%1, %2};" : "=l"(r) : "f"(a), "f"(b)); return r;
}
__device__ __forceinline__ u64 bcast2(float a){
    u64 r; asm("mov.b64 %0, {%1, %1};" : "=l"(r) : "f"(a)); return r;
}
__device__ __forceinline__ float2 upk(u64 v){
    float2 f; asm("mov.b64 {%0, %1}, %2;" : "=f"(f.x), "=f"(f.y) : "l"(v)); return f;
}
__device__ __forceinline__ void ffma2(u64 &d, u64 a, u64 b){
    asm("fma.rn.f32x2 %0, %1, %2, %0;" : "+l"(d) : "l"(a), "l"(b));
}

// ---------------- scratch (device globals; no allocation allowed) ----------
__device__ float g_off  [BB*18*HWSZ];
__device__ float g_mask [BB*9 *HWSZ];
__device__ float g_xd   [BB*CCH*HWSZ];
__device__ float g_xa   [BB*CCH*HWSZ];
__device__ float g_r1   [BB*256*HWSZ];
__device__ float g_xr   [BB*CCH*HWSZ];
__device__ float g_n1   [BB*32*HWSZ];
__device__ float g_n2   [BB*32*HWSZ];
__device__ float g_camean[BB*CCH];
__device__ float g_ca   [BB*CCH];

// transposed weights (output-channel contiguous)
__device__ float g_woffT[64*9*28];    // [c][k][o pad28]
__device__ float g_wdcT [9*64*64];    // [k][c][o]
__device__ float g_wr1T [64*256];     // [c][o]
__device__ float g_wr2T [256*9*64];   // [c][k][o]
__device__ float g_wn1T [64*32];      // [c][o]
__device__ float g_wn3T [32*64];      // [c][o]

__device__ __forceinline__ float leakyf(float v){ return v >= 0.f ? v : 0.1f*v; }
__device__ __forceinline__ float sigmf(float v){ return 1.f/(1.f+__expf(-v)); }

// ---------------- weight transpose prep ------------------------------------
__global__ void k_prep(const float* __restrict__ w_off, const float* __restrict__ w_dc,
                       const float* __restrict__ w_r1,  const float* __restrict__ w_r2,
                       const float* __restrict__ w_n1,  const float* __restrict__ w_n3){
    int t = blockIdx.x*blockDim.x + threadIdx.x;
    int nt = gridDim.x*blockDim.x;
    for (int i=t;i<64*9*28;i+=nt){ int o=i%28; int k=(i/28)%9; int c=i/(28*9);
        g_woffT[i] = (o<27) ? w_off[(o*64+c)*9+k] : 0.f; }
    for (int i=t;i<9*64*64;i+=nt){ int o=i%64; int c=(i/64)%64; int k=i/(64*64);
        g_wdcT[i] = w_dc[(o*64+c)*9+k]; }
    for (int i=t;i<64*256;i+=nt){ int o=i%256; int c=i/256; g_wr1T[i]=w_r1[o*64+c]; }
    for (int i=t;i<256*9*64;i+=nt){ int o=i%64; int k=(i/64)%9; int c=i/(64*9);
        g_wr2T[i] = w_r2[(o*256+c)*9+k]; }
    for (int i=t;i<64*32;i+=nt){ int o=i%32; int c=i/32; g_wn1T[i]=w_n1[o*64+c]; }
    for (int i=t;i<32*64;i+=nt){ int o=i%64; int c=i/64; g_wn3T[i]=w_n3[o*32+c]; }
}

// ---------------- offset conv: 3x3 64->27, leaky, split off/mask ------------
__global__ void k_off(const float* __restrict__ x, const float* __restrict__ b_off){
    __shared__ __align__(16) float sW[16*9*28];      // 16.1KB
    int p = blockIdx.x*blockDim.x + threadIdx.x;
    bool act = p < NPIX;
    int b=0,h=0,w=0,hw=0;
    if (act){ b=p/HWSZ; hw=p%HWSZ; h=hw/WWD; w=hw%WWD; }
    u64 acc[14];
    #pragma unroll
    for (int j=0;j<13;j++) acc[j] = pk2(b_off[2*j], b_off[2*j+1]);
    acc[13] = pk2(b_off[26], 0.f);
    int toff[9]; bool tv[9];
    #pragma unroll
    for (int k=0;k<9;k++){
        int hy=h+k/3-1, wx=w+k%3-1;
        tv[k] = (hy>=0 && hy<HH && wx>=0 && wx<WWD);
        toff[k] = tv[k] ? hy*WWD+wx : 0;
    }
    for (int cc=0; cc<4; cc++){
        for (int j=threadIdx.x; j<16*9*28; j+=blockDim.x) sW[j]=g_woffT[cc*16*9*28 + j];
        __syncthreads();
        if (act){
            const float* xb = x + (b*64 + cc*16)*HWSZ;
            for (int c=0;c<16;c++){
                const float* xc = xb + c*HWSZ;
                float xv[9];
                #pragma unroll
                for (int k=0;k<9;k++) xv[k] = tv[k] ? xc[toff[k]] : 0.f;
                #pragma unroll
                for (int k=0;k<9;k++){
                    u64 vp = bcast2(xv[k]);
                    const ulonglong2* wp = (const ulonglong2*)&sW[c*252 + k*28];
                    #pragma unroll
                    for (int j=0;j<7;j++){
                        ulonglong2 ww = wp[j];
                        ffma2(acc[2*j],   vp, ww.x);
                        ffma2(acc[2*j+1], vp, ww.y);
                    }
                }
            }
        }
        __syncthreads();
    }
    if (act){
        float o27[28];
        #pragma unroll
        for (int j=0;j<14;j++){ float2 f=upk(acc[j]); o27[2*j]=f.x; o27[2*j+1]=f.y; }
        #pragma unroll
        for (int o=0;o<18;o++) g_off[(b*18+o)*HWSZ+hw] = leakyf(o27[o]);
        #pragma unroll
        for (int o=0;o<9;o++)  g_mask[(b*9+o)*HWSZ+hw] = sigmf(leakyf(o27[18+o]));
    }
}

// ---------------- deformable conv 64->64 -----------------------------------
__global__ void k_dc(const float* __restrict__ x, const float* __restrict__ b_dc){
    __shared__ __align__(16) float sW[64*64];        // 16KB, [c][o] for current k
    int p = blockIdx.x*blockDim.x + threadIdx.x;
    bool act = p < NPIX;
    int b=0,h=0,w=0,hw=0;
    if (act){ b=p/HWSZ; hw=p%HWSZ; h=hw/WWD; w=hw%WWD; }
    u64 acc[32];
    #pragma unroll
    for (int j=0;j<32;j++) acc[j]=0ULL;
    for (int k=0;k<9;k++){
        for (int j=threadIdx.x;j<64*64;j+=blockDim.x) sW[j]=g_wdcT[k*64*64+j];
        __syncthreads();
        if (act){
            float dy = g_off[(b*18+2*k  )*HWSZ+hw];
            float dx = g_off[(b*18+2*k+1)*HWSZ+hw];
            float m  = g_mask[(b*9+k)*HWSZ+hw];
            float py = (float)h + (float)(k/3-1) + dy;
            float px = (float)w + (float)(k%3-1) + dx;
            float y0f = floorf(py), x0f = floorf(px);
            float wy = py - y0f,  wx = px - x0f;
            int y0=(int)y0f, x0=(int)x0f, y1=y0+1, x1=x0+1;
            bool vy0=(y0>=0&&y0<HH), vy1=(y1>=0&&y1<HH);
            bool vx0=(x0>=0&&x0<WWD), vx1=(x1>=0&&x1<WWD);
            float w00=(1.f-wy)*(1.f-wx)*((vy0&&vx0)?m:0.f);
            float w01=(1.f-wy)*wx      *((vy0&&vx1)?m:0.f);
            float w10=wy*(1.f-wx)      *((vy1&&vx0)?m:0.f);
            float w11=wy*wx            *((vy1&&vx1)?m:0.f);
            int cy0=min(max(y0,0),HH-1), cy1=min(max(y1,0),HH-1);
            int cx0=min(max(x0,0),WWD-1), cx1=min(max(x1,0),WWD-1);
            int i00=cy0*WWD+cx0, i01=cy0*WWD+cx1, i10=cy1*WWD+cx0, i11=cy1*WWD+cx1;
            const float* xb = x + b*64*HWSZ;
            for (int c=0;c<64;c++){
                const float* xc = xb + c*HWSZ;
                float v = w00*xc[i00]+w01*xc[i01]+w10*xc[i10]+w11*xc[i11];
                u64 vp = bcast2(v);
                const ulonglong2* wp = (const ulonglong2*)&sW[c*64];
                #pragma unroll
                for (int j=0;j<16;j++){
                    ulonglong2 ww = wp[j];
                    ffma2(acc[2*j],   vp, ww.x);
                    ffma2(acc[2*j+1], vp, ww.y);
                }
            }
        }
        __syncthreads();
    }
    if (act){
        #pragma unroll
        for (int j=0;j<32;j++){
            float2 f=upk(acc[j]);
            g_xd[(b*64+2*j  )*HWSZ+hw] = f.x + b_dc[2*j];
            g_xd[(b*64+2*j+1)*HWSZ+hw] = f.y + b_dc[2*j+1];
        }
    }
}

// ---------------- channel-attention mean reduce ------------------------------
__global__ void k_ca_red(){
    int bc = blockIdx.x;               // 0..255  (b*64+c)
    const float4* src = (const float4*)(g_xd + (size_t)bc*HWSZ);
    float s = 0.f;
    for (int i=threadIdx.x;i<HWSZ/4;i+=blockDim.x){
        float4 v = src[i]; s += (v.x+v.y)+(v.z+v.w);
    }
    __shared__ float red[256];
    red[threadIdx.x]=s; __syncthreads();
    for (int st=128;st>0;st>>=1){ if (threadIdx.x<st) red[threadIdx.x]+=red[threadIdx.x+st]; __syncthreads(); }
    if (threadIdx.x==0) g_camean[bc] = red[0]*(1.f/(float)HWSZ);
}

// ---------------- channel-attention MLP (tiny) ------------------------------
__global__ void k_ca_mlp(const float* __restrict__ w_ca1, const float* __restrict__ b_ca1,
                         const float* __restrict__ w_ca2, const float* __restrict__ b_ca2){
    __shared__ float hid[4*8];
    int t = threadIdx.x;
    if (t<32){ int b=t/8, j=t%8;
        float s = b_ca1[j];
        for (int c=0;c<64;c++) s += w_ca1[j*64+c]*g_camean[b*64+c];
        hid[b*8+j] = fmaxf(s,0.f);
    }
    __syncthreads();
    if (t<256){ int b=t/64, o=t%64;
        float s = b_ca2[o];
        #pragma unroll
        for (int j=0;j<8;j++) s += w_ca2[o*8+j]*hid[b*8+j];
        g_ca[t] = sigmf(s);
    }
}

// ---------------- spatial attention + xa = xd*(ca+sa) ------------------------
__global__ void k_sa_xa(const float* __restrict__ w_sa, const float* __restrict__ b_sa){
    __shared__ float sW[64*9];
    for (int j=threadIdx.x;j<576;j+=blockDim.x) sW[j]=w_sa[j];
    __syncthreads();
    int p = blockIdx.x*blockDim.x + threadIdx.x;
    if (p>=NPIX) return;
    int b=p/HWSZ, hw=p%HWSZ, h=hw/WWD, w=hw%WWD;
    int toff[9]; bool tv[9];
    #pragma unroll
    for (int k=0;k<9;k++){
        int hy=h+k/3-1, wx=w+k%3-1;
        tv[k]=(hy>=0&&hy<HH&&wx>=0&&wx<WWD);
        toff[k]=tv[k]?hy*WWD+wx:0;
    }
    float s = b_sa[0];
    const float* xb = g_xd + b*64*HWSZ;
    for (int c=0;c<64;c++){
        const float* xc = xb + c*HWSZ;
        #pragma unroll
        for (int k=0;k<9;k++) if (tv[k]) s += xc[toff[k]]*sW[c*9+k];
    }
    s = sigmf(s);
    for (int c=0;c<64;c++){
        float scale = g_ca[b*64+c] + s;
        g_xa[(b*64+c)*HWSZ+hw] = xb[c*HWSZ+hw]*scale;
    }
}

// ---------------- r1: conv1x1 64->256 + leaky (oc chunks of 64) --------------
__global__ void k_r1(const float* __restrict__ b_r1){
    __shared__ __align__(16) float sW[64*64];
    int oc0 = blockIdx.y*64;
    for (int j=threadIdx.x;j<4096;j+=blockDim.x){ int c=j>>6, o=j&63; sW[j]=g_wr1T[c*256+oc0+o]; }
    __syncthreads();
    int p = blockIdx.x*blockDim.x + threadIdx.x;
    if (p>=NPIX) return;
    int b=p/HWSZ, hw=p%HWSZ;
    u64 acc[32];
    #pragma unroll
    for (int j=0;j<32;j++) acc[j]=pk2(b_r1[oc0+2*j], b_r1[oc0+2*j+1]);
    const float* xb = g_xa + b*64*HWSZ + hw;
    for (int c=0;c<64;c++){
        u64 vp = bcast2(xb[(size_t)c*HWSZ]);
        const ulonglong2* wp = (const ulonglong2*)&sW[c*64];
        #pragma unroll
        for (int j=0;j<16;j++){
            ulonglong2 ww = wp[j];
            ffma2(acc[2*j],   vp, ww.x);
            ffma2(acc[2*j+1], vp, ww.y);
        }
    }
    float* ob = g_r1 + ((size_t)b*256+oc0)*HWSZ + hw;
    #pragma unroll
    for (int j=0;j<32;j++){
        float2 f=upk(acc[j]);
        ob[(size_t)(2*j  )*HWSZ] = leakyf(f.x);
        ob[(size_t)(2*j+1)*HWSZ] = leakyf(f.y);
    }
}

// ---------------- r2: conv3x3 256->64 ----------------------------------------
__global__ void k_r2(const float* __restrict__ b_r2){
    __shared__ __align__(16) float sW[16*9*64];      // 36.9KB
    int p = blockIdx.x*blockDim.x + threadIdx.x;
    bool act = p<NPIX;
    int b=0,h=0,w=0,hw=0;
    if (act){ b=p/HWSZ; hw=p%HWSZ; h=hw/WWD; w=hw%WWD; }
    int toff[9]; bool tv[9];
    #pragma unroll
    for (int k=0;k<9;k++){
        int hy=h+k/3-1, wx=w+k%3-1;
        tv[k]=(hy>=0&&hy<HH&&wx>=0&&wx<WWD);
        toff[k]=tv[k]?hy*WWD+wx:0;
    }
    u64 acc[32];
    #pragma unroll
    for (int j=0;j<32;j++) acc[j]=0ULL;
    for (int cc=0; cc<16; cc++){
        for (int j=threadIdx.x;j<16*9*64;j+=blockDim.x) sW[j]=g_wr2T[cc*16*9*64 + j];
        __syncthreads();
        if (act){
            const float* xb = g_r1 + ((size_t)b*256 + cc*16)*HWSZ;
            for (int c=0;c<16;c++){
                const float* xc = xb + (size_t)c*HWSZ;
                float xv[9];
                #pragma unroll
                for (int k=0;k<9;k++) xv[k] = tv[k] ? xc[toff[k]] : 0.f;
                #pragma unroll
                for (int k=0;k<9;k++){
                    u64 vp = bcast2(xv[k]);
                    const ulonglong2* wp = (const ulonglong2*)&sW[c*576 + k*64];
                    #pragma unroll
                    for (int j=0;j<16;j++){
                        ulonglong2 ww = wp[j];
                        ffma2(acc[2*j],   vp, ww.x);
                        ffma2(acc[2*j+1], vp, ww.y);
                    }
                }
            }
        }
        __syncthreads();
    }
    if (act){
        #pragma unroll
        for (int j=0;j<32;j++){
            float2 f=upk(acc[j]);
            g_xr[((size_t)b*64+2*j  )*HWSZ+hw] = f.x + b_r2[2*j];
            g_xr[((size_t)b*64+2*j+1)*HWSZ+hw] = f.y + b_r2[2*j+1];
        }
    }
}

// ---------------- n1: conv1x1 64->32 ----------------------------------------
__global__ void k_n1(const float* __restrict__ b_n1){
    __shared__ __align__(16) float sW[64*32];        // 8KB
    for (int j=threadIdx.x;j<2048;j+=blockDim.x) sW[j]=g_wn1T[j];
    __syncthreads();
    int p = blockIdx.x*blockDim.x + threadIdx.x;
    if (p>=NPIX) return;
    int b=p/HWSZ, hw=p%HWSZ;
    u64 acc[16];
    #pragma unroll
    for (int j=0;j<16;j++) acc[j]=pk2(b_n1[2*j], b_n1[2*j+1]);
    const float* xb = g_xa + (size_t)b*64*HWSZ + hw;
    for (int c=0;c<64;c++){
        u64 vp = bcast2(xb[(size_t)c*HWSZ]);
        const ulonglong2* wp=(const ulonglong2*)&sW[c*32];
        #pragma unroll
        for (int j=0;j<8;j++){
            ulonglong2 ww=wp[j];
            ffma2(acc[2*j],   vp, ww.x);
            ffma2(acc[2*j+1], vp, ww.y);
        }
    }
    float* ob = g_n1 + (size_t)b*32*HWSZ + hw;
    #pragma unroll
    for (int j=0;j<16;j++){
        float2 f=upk(acc[j]);
        ob[(size_t)(2*j  )*HWSZ]=f.x;
        ob[(size_t)(2*j+1)*HWSZ]=f.y;
    }
}

// ---------------- n2: depthwise 3x3 (32 ch) ----------------------------------
__global__ void k_n2(const float* __restrict__ w_n2, const float* __restrict__ b_n2){
    __shared__ float sW[32*9];
    for (int j=threadIdx.x;j<288;j+=blockDim.x) sW[j]=w_n2[j];
    __syncthreads();
    int p = blockIdx.x*blockDim.x + threadIdx.x;
    if (p>=NPIX) return;
    int b=p/HWSZ, hw=p%HWSZ, h=hw/WWD, w=hw%WWD;
    int toff[9]; bool tv[9];
    #pragma unroll
    for (int k=0;k<9;k++){
        int hy=h+k/3-1, wx=w+k%3-1;
        tv[k]=(hy>=0&&hy<HH&&wx>=0&&wx<WWD);
        toff[k]=tv[k]?hy*WWD+wx:0;
    }
    const float* xb = g_n1 + (size_t)b*32*HWSZ;
    float* ob = g_n2 + (size_t)b*32*HWSZ;
    for (int c=0;c<32;c++){
        const float* xc = xb + (size_t)c*HWSZ;
        float acc = b_n2[c];
        #pragma unroll
        for (int k=0;k<9;k++) if (tv[k]) acc += xc[toff[k]]*sW[c*9+k];
        ob[(size_t)c*HWSZ+hw]=acc;
    }
}

// ---------------- final: conv1x1 32->64 (n3) + x + xr -> out ------------------
__global__ void k_final(const float* __restrict__ x, const float* __restrict__ b_n3,
                        float* __restrict__ out){
    __shared__ __align__(16) float sW[32*64];        // 8KB
    for (int j=threadIdx.x;j<2048;j+=blockDim.x) sW[j]=g_wn3T[j];
    __syncthreads();
    int p = blockIdx.x*blockDim.x + threadIdx.x;
    if (p>=NPIX) return;
    int b=p/HWSZ, hw=p%HWSZ;
    u64 acc[32];
    #pragma unroll
    for (int j=0;j<32;j++) acc[j]=pk2(b_n3[2*j], b_n3[2*j+1]);
    const float* xb = g_n2 + (size_t)b*32*HWSZ + hw;
    for (int c=0;c<32;c++){
        u64 vp = bcast2(xb[(size_t)c*HWSZ]);
        const ulonglong2* wp=(const ulonglong2*)&sW[c*64];
        #pragma unroll
        for (int j=0;j<16;j++){
            ulonglong2 ww=wp[j];
            ffma2(acc[2*j],   vp, ww.x);
            ffma2(acc[2*j+1], vp, ww.y);
        }
    }
    const float* xin = x + (size_t)b*64*HWSZ + hw;
    const float* xr  = g_xr + (size_t)b*64*HWSZ + hw;
    float* ob = out + (size_t)b*64*HWSZ + hw;
    #pragma unroll
    for (int j=0;j<32;j++){
        float2 f=upk(acc[j]);
        ob[(size_t)(2*j  )*HWSZ] = xin[(size_t)(2*j  )*HWSZ] + xr[(size_t)(2*j  )*HWSZ] + f.x;
        ob[(size_t)(2*j+1)*HWSZ] = xin[(size_t)(2*j+1)*HWSZ] + xr[(size_t)(2*j+1)*HWSZ] + f.y;
    }
}

// ---------------- launch ------------------------------------------------------
extern "C" void kernel_launch(void* const* d_in, const int* in_sizes, int n_in,
                              void* d_out, int out_size){
    const float* x     = (const float*)d_in[0];
    const float* w_off = (const float*)d_in[1];
    const float* b_off = (const float*)d_in[2];
    const float* w_dc  = (const float*)d_in[3];
    const float* b_dc  = (const float*)d_in[4];
    const float* w_ca1 = (const float*)d_in[5];
    const float* b_ca1 = (const float*)d_in[6];
    const float* w_ca2 = (const float*)d_in[7];
    const float* b_ca2 = (const float*)d_in[8];
    const float* w_sa  = (const float*)d_in[9];
    const float* b_sa  = (const float*)d_in[10];
    const float* w_r1  = (const float*)d_in[11];
    const float* b_r1  = (const float*)d_in[12];
    const float* w_r2  = (const float*)d_in[13];
    const float* b_r2  = (const float*)d_in[14];
    const float* w_n1  = (const float*)d_in[15];
    const float* b_n1  = (const float*)d_in[16];
    const float* w_n2  = (const float*)d_in[17];
    const float* b_n2  = (const float*)d_in[18];
    const float* w_n3  = (const float*)d_in[19];
    const float* b_n3  = (const float*)d_in[20];
    float* out = (float*)d_out;

    const int TPB = 256;
    const int GP  = (NPIX + TPB - 1)/TPB;   // 576

    k_prep<<<64, 256>>>(w_off, w_dc, w_r1, w_r2, w_n1, w_n3);
    k_off<<<GP, TPB>>>(x, b_off);
    k_dc<<<GP, TPB>>>(x, b_dc);
    k_ca_red<<<BB*CCH, 256>>>();
    k_ca_mlp<<<1, 256>>>(w_ca1, b_ca1, w_ca2, b_ca2);
    k_sa_xa<<<GP, TPB>>>(w_sa, b_sa);
    k_r1<<<dim3(GP,4), TPB>>>(b_r1);
    k_r2<<<GP, TPB>>>(b_r2);
    k_n1<<<GP, TPB>>>(b_n1);
    k_n2<<<GP, TPB>>>(w_n2, b_n2);
    k_final<<<GP, TPB>>>(x, b_n3, out);
}